// round 15
// baseline (speedup 1.0000x reference)
#include <cuda_runtime.h>
#include <cuda_fp16.h>
#include <math.h>
#include <stdint.h>

#define NE 8
#define DDIM 1024
#define IDIM 4096
#define NTOK 8192
#define NROWS (NTOK*2)
#define OUT_ELEMS (NTOK*DDIM)

// ---------------- scratch (device globals; ONLY referenced from device code) ----------------
__device__ int   g_cnt[NE];
__device__ int   g_list[NE*NTOK];
__device__ float g_rw[NROWS];
__device__ float g_pp[1024*NE];
__device__ __half g_h[NROWS*IDIM];       // fp16 h (gemm2 A operand)
__device__ float g_y[NROWS*DDIM];
__device__ __half g_x16[NTOK*DDIM];      // fp16 x
__device__ __half g_wg16[NE*DDIM*IDIM];  // fp16 weights
__device__ __half g_wu16[NE*DDIM*IDIM];
__device__ __half g_wd16[NE*IDIM*DDIM];

// ---------------- helpers ----------------
__device__ __forceinline__ uint32_t ph2(float a, float b) {
    __half2 h = __floats2half2_rn(a, b);
    return *reinterpret_cast<uint32_t*>(&h);
}
__device__ __forceinline__ uint4 pk8(float4 a, float4 b) {
    return make_uint4(ph2(a.x,a.y), ph2(a.z,a.w), ph2(b.x,b.y), ph2(b.z,b.w));
}
__device__ __forceinline__ void ldm4(uint32_t* r, uint32_t a) {
    asm volatile("ldmatrix.sync.aligned.m8n8.x4.shared.b16 {%0,%1,%2,%3}, [%4];"
        : "=r"(r[0]), "=r"(r[1]), "=r"(r[2]), "=r"(r[3]) : "r"(a));
}
__device__ __forceinline__ void ldm2t(uint32_t* r, uint32_t a) {
    asm volatile("ldmatrix.sync.aligned.m8n8.x2.trans.shared.b16 {%0,%1}, [%2];"
        : "=r"(r[0]), "=r"(r[1]) : "r"(a));
}
__device__ __forceinline__ void mmaf16(float* c, const uint32_t* a, const uint32_t* b) {
    asm volatile(
        "mma.sync.aligned.m16n8k16.row.col.f32.f16.f16.f32 "
        "{%0,%1,%2,%3}, {%4,%5,%6,%7}, {%8,%9}, {%0,%1,%2,%3};"
        : "+f"(c[0]), "+f"(c[1]), "+f"(c[2]), "+f"(c[3])
        : "r"(a[0]), "r"(a[1]), "r"(a[2]), "r"(a[3]), "r"(b[0]), "r"(b[1]));
}
__device__ __forceinline__ uint32_t sgen(const void* p) {
    return (uint32_t)__cvta_generic_to_shared(p);
}
// cp.async 16B; src_sz in {0,16} (0 => zero-fill, src not dereferenced)
__device__ __forceinline__ void cpa16(uint32_t dst, const void* src, uint32_t src_sz) {
    asm volatile(
        "{ .reg .u64 gp; cvta.to.global.u64 gp, %1; "
        "cp.async.cg.shared.global [%0], [gp], 16, %2; }"
        :: "r"(dst), "l"(src), "r"(src_sz) : "memory");
}
#define CPA_COMMIT() asm volatile("cp.async.commit_group;" ::: "memory")
#define CPA_WAIT1()  asm volatile("cp.async.wait_group 1;" ::: "memory")
#define CPA_WAIT0()  asm volatile("cp.async.wait_group 0;" ::: "memory")

// ---------------- small kernels ----------------
__global__ void zero_kernel() { if (threadIdx.x < NE) g_cnt[threadIdx.x] = 0; }

__global__ void __launch_bounds__(256) conv_x(const float* __restrict__ src) {
    size_t i = ((size_t)blockIdx.x * 256 + threadIdx.x) * 8;
    float4 a = *(const float4*)(src + i);
    float4 b = *(const float4*)(src + i + 4);
    *(uint4*)(g_x16 + i) = pk8(a, b);
}
__global__ void __launch_bounds__(256) conv_wg(const float* __restrict__ src) {
    size_t i = ((size_t)blockIdx.x * 256 + threadIdx.x) * 8;
    float4 a = *(const float4*)(src + i);
    float4 b = *(const float4*)(src + i + 4);
    *(uint4*)(g_wg16 + i) = pk8(a, b);
}
__global__ void __launch_bounds__(256) conv_wu(const float* __restrict__ src) {
    size_t i = ((size_t)blockIdx.x * 256 + threadIdx.x) * 8;
    float4 a = *(const float4*)(src + i);
    float4 b = *(const float4*)(src + i + 4);
    *(uint4*)(g_wu16 + i) = pk8(a, b);
}
__global__ void __launch_bounds__(256) conv_wd(const float* __restrict__ src) {
    size_t i = ((size_t)blockIdx.x * 256 + threadIdx.x) * 8;
    float4 a = *(const float4*)(src + i);
    float4 b = *(const float4*)(src + i + 4);
    *(uint4*)(g_wd16 + i) = pk8(a, b);
}

__global__ void __launch_bounds__(256) router_kernel(const float* __restrict__ x,
                                                     const float* __restrict__ wgate) {
    __shared__ float sw[NE*DDIM];
    __shared__ float sprob[8][NE];
    int tid = threadIdx.x;
    for (int i = tid; i < NE*DDIM; i += 256) sw[i] = wgate[i];
    __syncthreads();
    int warp = tid >> 5, lane = tid & 31;
    int n = blockIdx.x * 8 + warp;
    const float* xr = x + (size_t)n * DDIM;
    float xv[32];
#pragma unroll
    for (int i = 0; i < 32; i++) xv[i] = xr[i*32 + lane];
    float p[NE]; float mx = -1e30f;
#pragma unroll
    for (int e = 0; e < NE; e++) {
        float acc = 0.f;
        const float* swe = sw + e*DDIM;
#pragma unroll
        for (int i = 0; i < 32; i++) acc += xv[i] * swe[i*32 + lane];
#pragma unroll
        for (int o = 16; o > 0; o >>= 1) acc += __shfl_xor_sync(0xffffffffu, acc, o);
        p[e] = acc; mx = fmaxf(mx, acc);
    }
    float se = 0.f;
#pragma unroll
    for (int e = 0; e < NE; e++) { p[e] = expf(p[e] - mx); se += p[e]; }
    float inv = 1.f / se;
#pragma unroll
    for (int e = 0; e < NE; e++) p[e] *= inv;
    int e0 = 0;
#pragma unroll
    for (int e = 1; e < NE; e++) if (p[e] > p[e0]) e0 = e;
    int e1 = (e0 == 0) ? 1 : 0;
#pragma unroll
    for (int e = 0; e < NE; e++) if (e != e0 && e != e1 && p[e] > p[e1]) e1 = e;
    if (lane == 0) {
        float w0 = p[e0], w1 = p[e1], s = w0 + w1;
        g_rw[n*2] = w0 / s; g_rw[n*2+1] = w1 / s;
        int p0 = atomicAdd(&g_cnt[e0], 1); g_list[e0*NTOK + p0] = n*2;
        int p1 = atomicAdd(&g_cnt[e1], 1); g_list[e1*NTOK + p1] = n*2 + 1;
#pragma unroll
        for (int e = 0; e < NE; e++) sprob[warp][e] = p[e];
    }
    __syncthreads();
    if (tid == 0) {
#pragma unroll
        for (int e = 0; e < NE; e++) {
            float s = 0.f;
            for (int w = 0; w < 8; w++) s += sprob[w][e];
            g_pp[blockIdx.x*NE + e] = s;
        }
    }
}

// ---------------- GEMM geometry (fp16, 3-stage dynamic smem) ----------------
#define A_ST2  40            // 128x32 fp16, 80B rows
#define A_H2   (128*A_ST2)   // 5120 halves
#define B1_ST2 72            // 32x64 fp16, 144B rows
#define B1_H2  (32*B1_ST2)   // 2304
#define ST1H   (A_H2 + 2*B1_H2)   // 9728 halves per stage
#define G1_SMEM (3*ST1H*2)        // 58368 B
#define NT1 32
#define B2_ST2 136           // 32x128 fp16, 272B rows
#define B2_H2  (32*B2_ST2)   // 4352
#define ST2H   (A_H2 + B2_H2)     // 9472 halves per stage
#define G2_SMEM (3*ST2H*2)        // 56832 B
#define NT2 128

// ---------------- GEMM1: 128 x (64g + 64u) x 1024, cp.async 3-stage, 2 CTA/SM ----------------
__global__ void __launch_bounds__(256, 2) gemm1_mma() {
    extern __shared__ __align__(16) __half dsm[];
    __shared__ int rows_s[128];

    int e = blockIdx.z;
    int cnt = g_cnt[e];
    int m0 = blockIdx.x * 128;
    if (m0 >= cnt) return;
    int n0 = blockIdx.y * 64;

    int tid = threadIdx.x, wid = tid >> 5, lane = tid & 31;
    if (tid < 128) rows_s[tid] = (m0 + tid < cnt) ? g_list[e*NTOK + m0 + tid] : -1;
    __syncthreads();

    int ar = tid >> 1, ach = (tid & 1) * 16;
    int arid = rows_s[ar];
    uint32_t asz = (arid >= 0) ? 16u : 0u;
    const __half* aptr = g_x16 + (size_t)((arid >= 0) ? (arid >> 1) : 0) * DDIM;
    int bk = tid >> 3, bn = tid & 7;
    const __half* bgp = g_wg16 + ((size_t)e * DDIM + bk) * IDIM + n0 + bn*8;
    const __half* bup = g_wu16 + ((size_t)e * DDIM + bk) * IDIM + n0 + bn*8;

    int wm = wid & 1, wn = wid >> 1;
    int g = lane >> 2, tig = lane & 3;
    int q = lane >> 3;
    int rA = (q & 1) * 8 + (lane & 7);
    int cA = (q >> 1) * 8;
    int rB = lane & 15;

    uint32_t s0 = sgen(dsm);
    uint32_t abase = s0 + ((wm*64 + rA)*A_ST2 + cA)*2;
    uint32_t gbase = s0 + (A_H2 + rB*B1_ST2 + wn*16)*2;
    uint32_t ubase = s0 + (A_H2 + B1_H2 + rB*B1_ST2 + wn*16)*2;
    // cp.async dst (byte) offsets within a stage
    uint32_t dA0 = s0 + (ar*A_ST2 + ach)*2;
    uint32_t dA1 = dA0 + 16;
    uint32_t dBg = s0 + (A_H2 + bk*B1_ST2 + bn*8)*2;
    uint32_t dBu = s0 + (A_H2 + B1_H2 + bk*B1_ST2 + bn*8)*2;

    float cg[4][2][4], cu[4][2][4];
#pragma unroll
    for (int a = 0; a < 4; a++)
#pragma unroll
        for (int b = 0; b < 2; b++)
#pragma unroll
            for (int c = 0; c < 4; c++) { cg[a][b][c] = 0.f; cu[a][b][c] = 0.f; }

#define ISSUE1(S, KT) do {                                                      \
    uint32_t so_ = (uint32_t)(S) * (ST1H*2);                                    \
    int kf_ = (KT) * 32;                                                        \
    cpa16(dA0 + so_, aptr + kf_ + ach, asz);                                    \
    cpa16(dA1 + so_, aptr + kf_ + ach + 8, asz);                                \
    cpa16(dBg + so_, bgp + (size_t)kf_ * IDIM, 16u);                            \
    cpa16(dBu + so_, bup + (size_t)kf_ * IDIM, 16u);                            \
    CPA_COMMIT();                                                               \
} while (0)

#define COMP1(S) do {                                                           \
    uint32_t so_ = (uint32_t)(S) * (ST1H*2);                                    \
    uint32_t ab_ = abase + so_;                                                 \
    uint32_t gb_ = gbase + so_;                                                 \
    uint32_t ub_ = ubase + so_;                                                 \
    _Pragma("unroll")                                                           \
    for (int sp = 0; sp < 2; sp++) {                                            \
        uint32_t af[4][4], gf[2][2], uf[2][2];                                  \
        _Pragma("unroll")                                                       \
        for (int mi = 0; mi < 4; mi++)                                          \
            ldm4(af[mi], ab_ + (mi*16*A_ST2 + sp*16)*2);                        \
        _Pragma("unroll")                                                       \
        for (int p = 0; p < 2; p++) {                                           \
            ldm2t(gf[p], gb_ + (sp*16*B1_ST2 + p*8)*2);                         \
            ldm2t(uf[p], ub_ + (sp*16*B1_ST2 + p*8)*2);                         \
        }                                                                       \
        _Pragma("unroll")                                                       \
        for (int p = 0; p < 2; p++)                                             \
            _Pragma("unroll")                                                   \
            for (int mi = 0; mi < 4; mi++) {                                    \
                mmaf16(cg[mi][p], af[mi], gf[p]);                               \
                mmaf16(cu[mi][p], af[mi], uf[p]);                               \
            }                                                                   \
    }                                                                           \
} while (0)

    ISSUE1(0, 0);
    ISSUE1(1, 1);
    for (int kt = 0; kt < NT1; kt++) {
        if (kt == NT1 - 1) { CPA_WAIT0(); } else { CPA_WAIT1(); }
        __syncthreads();
        if (kt + 2 < NT1) ISSUE1((kt + 2) % 3, kt + 2);
        COMP1(kt % 3);
    }

    // epilogue: h = silu(gate)*up -> fp16
#pragma unroll
    for (int mi = 0; mi < 4; mi++) {
#pragma unroll
        for (int rh = 0; rh < 2; rh++) {
            int m = wm*64 + mi*16 + g + rh*8;
            int rid = rows_s[m];
            if (rid < 0) continue;
            __half2* hp = (__half2*)(g_h + (size_t)rid * IDIM + n0 + wn*16 + 2*tig);
#pragma unroll
            for (int p = 0; p < 2; p++) {
                float gv0 = cg[mi][p][rh*2+0], gv1 = cg[mi][p][rh*2+1];
                float uv0 = cu[mi][p][rh*2+0], uv1 = cu[mi][p][rh*2+1];
                float h0 = gv0 / (1.f + expf(-gv0)) * uv0;
                float h1 = gv1 / (1.f + expf(-gv1)) * uv1;
                hp[p*4] = __floats2half2_rn(h0, h1);
            }
        }
    }
}

// ---------------- GEMM2: 128 x 128 x 4096, cp.async 3-stage, 2 CTA/SM ----------------
__global__ void __launch_bounds__(256, 2) gemm2_mma() {
    extern __shared__ __align__(16) __half dsm[];
    __shared__ int rows_s[128];

    int e = blockIdx.z;
    int cnt = g_cnt[e];
    int m0 = blockIdx.x * 128;
    if (m0 >= cnt) return;
    int n0 = blockIdx.y * 128;

    int tid = threadIdx.x, wid = tid >> 5, lane = tid & 31;
    if (tid < 128) rows_s[tid] = (m0 + tid < cnt) ? g_list[e*NTOK + m0 + tid] : -1;
    __syncthreads();

    int ar = tid >> 1, ach = (tid & 1) * 16;
    int arid = rows_s[ar];
    uint32_t asz = (arid >= 0) ? 16u : 0u;
    const __half* aptr = g_h + (size_t)((arid >= 0) ? arid : 0) * IDIM;
    int bk = tid >> 3, bn = tid & 7;
    const __half* bp = g_wd16 + ((size_t)e * IDIM + bk) * DDIM + n0 + bn*16;

    int wm = wid & 1, wn = wid >> 1;
    int g = lane >> 2, tig = lane & 3;
    int q = lane >> 3;
    int rA = (q & 1) * 8 + (lane & 7);
    int cA = (q >> 1) * 8;
    int rB = lane & 15;

    uint32_t s0 = sgen(dsm);
    uint32_t abase = s0 + ((wm*64 + rA)*A_ST2 + cA)*2;
    uint32_t bbase = s0 + (A_H2 + rB*B2_ST2 + wn*32)*2;
    uint32_t dA0 = s0 + (ar*A_ST2 + ach)*2;
    uint32_t dA1 = dA0 + 16;
    uint32_t dB0 = s0 + (A_H2 + bk*B2_ST2 + bn*16)*2;
    uint32_t dB1 = dB0 + 16;

    float cc[4][4][4];
#pragma unroll
    for (int a = 0; a < 4; a++)
#pragma unroll
        for (int b = 0; b < 4; b++)
#pragma unroll
            for (int c = 0; c < 4; c++) cc[a][b][c] = 0.f;

#define ISSUE2(S, KT) do {                                                      \
    uint32_t so_ = (uint32_t)(S) * (ST2H*2);                                    \
    int kf_ = (KT) * 32;                                                        \
    cpa16(dA0 + so_, aptr + kf_ + ach, asz);                                    \
    cpa16(dA1 + so_, aptr + kf_ + ach + 8, asz);                                \
    cpa16(dB0 + so_, bp + (size_t)kf_ * DDIM, 16u);                             \
    cpa16(dB1 + so_, bp + (size_t)kf_ * DDIM + 8, 16u);                         \
    CPA_COMMIT();                                                               \
} while (0)

#define COMP2(S) do {                                                           \
    uint32_t so_ = (uint32_t)(S) * (ST2H*2);                                    \
    uint32_t ab_ = abase + so_;                                                 \
    uint32_t bb_ = bbase + so_;                                                 \
    _Pragma("unroll")                                                           \
    for (int sp = 0; sp < 2; sp++) {                                            \
        uint32_t af[4][4], bf[4][2];                                            \
        _Pragma("unroll")                                                       \
        for (int mi = 0; mi < 4; mi++)                                          \
            ldm4(af[mi], ab_ + (mi*16*A_ST2 + sp*16)*2);                        \
        _Pragma("unroll")                                                       \
        for (int p = 0; p < 4; p++)                                             \
            ldm2t(bf[p], bb_ + (sp*16*B2_ST2 + p*8)*2);                         \
        _Pragma("unroll")                                                       \
        for (int p = 0; p < 4; p++)                                             \
            _Pragma("unroll")                                                   \
            for (int mi = 0; mi < 4; mi++)                                      \
                mmaf16(cc[mi][p], af[mi], bf[p]);                               \
    }                                                                           \
} while (0)

    ISSUE2(0, 0);
    ISSUE2(1, 1);
    for (int kt = 0; kt < NT2; kt++) {
        if (kt == NT2 - 1) { CPA_WAIT0(); } else { CPA_WAIT1(); }
        __syncthreads();
        if (kt + 2 < NT2) ISSUE2((kt + 2) % 3, kt + 2);
        COMP2(kt % 3);
    }

#pragma unroll
    for (int mi = 0; mi < 4; mi++) {
#pragma unroll
        for (int rh = 0; rh < 2; rh++) {
            int m = wm*64 + mi*16 + g + rh*8;
            int rid = rows_s[m];
            if (rid < 0) continue;
            float w = g_rw[rid];
            float* yp = g_y + (size_t)rid * DDIM + n0 + wn*32 + 2*tig;
#pragma unroll
            for (int p = 0; p < 4; p++) {
                float v0 = cc[mi][p][rh*2+0] * w;
                float v1 = cc[mi][p][rh*2+1] * w;
                *(float2*)(yp + p*8) = make_float2(v0, v1);
            }
        }
    }
}

// ---------------- combine + aux ----------------
__global__ void __launch_bounds__(256) combine_kernel(float* __restrict__ out) {
    size_t idx = (size_t)blockIdx.x * 256 + threadIdx.x;
    size_t n = idx >> 8, off = idx & 255;
    const float4* y4 = (const float4*)g_y;
    float4 a = y4[(n*2)     * 256 + off];
    float4 b = y4[(n*2 + 1) * 256 + off];
    ((float4*)out)[idx] = make_float4(a.x+b.x, a.y+b.y, a.z+b.z, a.w+b.w);
}

__global__ void finalize_kernel(float* __restrict__ out, int has_aux) {
    __shared__ float fp[NE];
    int t = threadIdx.x;
    if (t < NE) {
        float s = 0.f;
        for (int b = 0; b < 1024; b++) s += g_pp[b*NE + t];
        float pmean = s / (float)NTOK;
        float f = (float)g_cnt[t] / (float)NROWS;
        fp[t] = f * pmean;
    }
    __syncthreads();
    if (t == 0 && has_aux) {
        float a = 0.f;
        for (int e = 0; e < NE; e++) a += fp[e];
        out[OUT_ELEMS] = 0.02f * (float)NE * a;
    }
}

extern "C" void kernel_launch(void* const* d_in, const int* in_sizes, int n_in,
                              void* d_out, int out_size) {
    const float* x     = (const float*)d_in[0];
    const float* wgate = (const float*)d_in[1];
    const float* wg    = (const float*)d_in[2];
    const float* wu    = (const float*)d_in[3];
    const float* wd    = (const float*)d_in[4];
    float* out = (float*)d_out;

    cudaFuncSetAttribute(gemm1_mma, cudaFuncAttributeMaxDynamicSharedMemorySize, G1_SMEM);
    cudaFuncSetAttribute(gemm2_mma, cudaFuncAttributeMaxDynamicSharedMemorySize, G2_SMEM);

    zero_kernel<<<1, 32>>>();
    router_kernel<<<1024, 256>>>(x, wgate);
    conv_x<<<NTOK*DDIM/2048, 256>>>(x);
    conv_wg<<<NE*DDIM*IDIM/2048, 256>>>(wg);
    conv_wu<<<NE*DDIM*IDIM/2048, 256>>>(wu);
    conv_wd<<<NE*IDIM*DDIM/2048, 256>>>(wd);
    gemm1_mma<<<dim3(64, 64, 8), 256, G1_SMEM>>>();
    gemm2_mma<<<dim3(64, 8, 8), 256, G2_SMEM>>>();
    combine_kernel<<<8192, 256>>>(out);
    finalize_kernel<<<1, 32>>>(out, out_size > OUT_ELEMS ? 1 : 0);
}

// round 16
// speedup vs baseline: 1.4115x; 1.4115x over previous
#include <cuda_runtime.h>
#include <cuda_fp16.h>
#include <math.h>
#include <stdint.h>

#define NE 8
#define DDIM 1024
#define IDIM 4096
#define NTOK 8192
#define NROWS (NTOK*2)
#define OUT_ELEMS (NTOK*DDIM)

// ---------------- scratch (device globals; ONLY referenced from device code) ----------------
__device__ int   g_cnt[NE];
__device__ int   g_list[NE*NTOK];
__device__ float g_rw[NROWS];
__device__ float g_pp[1024*NE];
__device__ __half g_h[NROWS*IDIM];       // fp16 h (gemm2 A operand)
__device__ __half g_x16[NTOK*DDIM];      // fp16 x
__device__ __half g_wg16[NE*DDIM*IDIM];  // fp16 weights
__device__ __half g_wu16[NE*DDIM*IDIM];
__device__ __half g_wd16[NE*IDIM*DDIM];

// ---------------- helpers ----------------
__device__ __forceinline__ uint32_t ph2(float a, float b) {
    __half2 h = __floats2half2_rn(a, b);
    return *reinterpret_cast<uint32_t*>(&h);
}
__device__ __forceinline__ uint4 pk8(float4 a, float4 b) {
    return make_uint4(ph2(a.x,a.y), ph2(a.z,a.w), ph2(b.x,b.y), ph2(b.z,b.w));
}
__device__ __forceinline__ void ldm4(uint32_t* r, uint32_t a) {
    asm volatile("ldmatrix.sync.aligned.m8n8.x4.shared.b16 {%0,%1,%2,%3}, [%4];"
        : "=r"(r[0]), "=r"(r[1]), "=r"(r[2]), "=r"(r[3]) : "r"(a));
}
__device__ __forceinline__ void ldm2t(uint32_t* r, uint32_t a) {
    asm volatile("ldmatrix.sync.aligned.m8n8.x2.trans.shared.b16 {%0,%1}, [%2];"
        : "=r"(r[0]), "=r"(r[1]) : "r"(a));
}
__device__ __forceinline__ void mmaf16(float* c, const uint32_t* a, const uint32_t* b) {
    asm volatile(
        "mma.sync.aligned.m16n8k16.row.col.f32.f16.f16.f32 "
        "{%0,%1,%2,%3}, {%4,%5,%6,%7}, {%8,%9}, {%0,%1,%2,%3};"
        : "+f"(c[0]), "+f"(c[1]), "+f"(c[2]), "+f"(c[3])
        : "r"(a[0]), "r"(a[1]), "r"(a[2]), "r"(a[3]), "r"(b[0]), "r"(b[1]));
}
__device__ __forceinline__ uint32_t sgen(const void* p) {
    return (uint32_t)__cvta_generic_to_shared(p);
}

// ---------------- small kernels ----------------
__global__ void zero_kernel() { if (threadIdx.x < NE) g_cnt[threadIdx.x] = 0; }

__global__ void __launch_bounds__(256) zero_out_kernel(float* __restrict__ out) {
    size_t i = ((size_t)blockIdx.x * 256 + threadIdx.x) * 4;
    ((float4*)out)[i >> 2] = make_float4(0.f, 0.f, 0.f, 0.f);
}

__global__ void __launch_bounds__(256) conv_x(const float* __restrict__ src) {
    size_t i = ((size_t)blockIdx.x * 256 + threadIdx.x) * 8;
    float4 a = *(const float4*)(src + i);
    float4 b = *(const float4*)(src + i + 4);
    *(uint4*)(g_x16 + i) = pk8(a, b);
}
__global__ void __launch_bounds__(256) conv_wg(const float* __restrict__ src) {
    size_t i = ((size_t)blockIdx.x * 256 + threadIdx.x) * 8;
    float4 a = *(const float4*)(src + i);
    float4 b = *(const float4*)(src + i + 4);
    *(uint4*)(g_wg16 + i) = pk8(a, b);
}
__global__ void __launch_bounds__(256) conv_wu(const float* __restrict__ src) {
    size_t i = ((size_t)blockIdx.x * 256 + threadIdx.x) * 8;
    float4 a = *(const float4*)(src + i);
    float4 b = *(const float4*)(src + i + 4);
    *(uint4*)(g_wu16 + i) = pk8(a, b);
}
__global__ void __launch_bounds__(256) conv_wd(const float* __restrict__ src) {
    size_t i = ((size_t)blockIdx.x * 256 + threadIdx.x) * 8;
    float4 a = *(const float4*)(src + i);
    float4 b = *(const float4*)(src + i + 4);
    *(uint4*)(g_wd16 + i) = pk8(a, b);
}

__global__ void __launch_bounds__(256) router_kernel(const float* __restrict__ x,
                                                     const float* __restrict__ wgate) {
    __shared__ float sw[NE*DDIM];
    __shared__ float sprob[8][NE];
    int tid = threadIdx.x;
    for (int i = tid; i < NE*DDIM; i += 256) sw[i] = wgate[i];
    __syncthreads();
    int warp = tid >> 5, lane = tid & 31;
    int n = blockIdx.x * 8 + warp;
    const float* xr = x + (size_t)n * DDIM;
    float xv[32];
#pragma unroll
    for (int i = 0; i < 32; i++) xv[i] = xr[i*32 + lane];
    float p[NE]; float mx = -1e30f;
#pragma unroll
    for (int e = 0; e < NE; e++) {
        float acc = 0.f;
        const float* swe = sw + e*DDIM;
#pragma unroll
        for (int i = 0; i < 32; i++) acc += xv[i] * swe[i*32 + lane];
#pragma unroll
        for (int o = 16; o > 0; o >>= 1) acc += __shfl_xor_sync(0xffffffffu, acc, o);
        p[e] = acc; mx = fmaxf(mx, acc);
    }
    float se = 0.f;
#pragma unroll
    for (int e = 0; e < NE; e++) { p[e] = expf(p[e] - mx); se += p[e]; }
    float inv = 1.f / se;
#pragma unroll
    for (int e = 0; e < NE; e++) p[e] *= inv;
    int e0 = 0;
#pragma unroll
    for (int e = 1; e < NE; e++) if (p[e] > p[e0]) e0 = e;
    int e1 = (e0 == 0) ? 1 : 0;
#pragma unroll
    for (int e = 0; e < NE; e++) if (e != e0 && e != e1 && p[e] > p[e1]) e1 = e;
    if (lane == 0) {
        float w0 = p[e0], w1 = p[e1], s = w0 + w1;
        g_rw[n*2] = w0 / s; g_rw[n*2+1] = w1 / s;
        int p0 = atomicAdd(&g_cnt[e0], 1); g_list[e0*NTOK + p0] = n*2;
        int p1 = atomicAdd(&g_cnt[e1], 1); g_list[e1*NTOK + p1] = n*2 + 1;
#pragma unroll
        for (int e = 0; e < NE; e++) sprob[warp][e] = p[e];
    }
    __syncthreads();
    if (tid == 0) {
#pragma unroll
        for (int e = 0; e < NE; e++) {
            float s = 0.f;
            for (int w = 0; w < 8; w++) s += sprob[w][e];
            g_pp[blockIdx.x*NE + e] = s;
        }
    }
}

// ---------------- GEMM geometry (fp16 smem, static) ----------------
#define A_ST2  40            // 128x32 fp16, 80B rows
#define B1_ST2 72            // 32x64 fp16, 144B rows
#define B2_ST2 136           // 32x128 fp16, 272B rows
#define NT1 32
#define NT2 128

// ---------------- GEMM1: 128 x (64g + 64u) x 1024, 2 CTA/SM ----------------
__global__ void __launch_bounds__(256, 2) gemm1_mma() {
    __shared__ __align__(16) __half As[2][128*A_ST2];
    __shared__ __align__(16) __half Bg[2][32*B1_ST2];
    __shared__ __align__(16) __half Bu[2][32*B1_ST2];
    __shared__ int rows_s[128];

    int e = blockIdx.z;
    int cnt = g_cnt[e];
    int m0 = blockIdx.x * 128;
    if (m0 >= cnt) return;
    int n0 = blockIdx.y * 64;

    int tid = threadIdx.x, wid = tid >> 5, lane = tid & 31;
    if (tid < 128) rows_s[tid] = (m0 + tid < cnt) ? g_list[e*NTOK + m0 + tid] : -1;
    __syncthreads();

    int ar = tid >> 1, ach = (tid & 1) * 16;     // A: row, fp16 col base
    int arid = rows_s[ar];
    const __half* aptr = (arid >= 0) ? (g_x16 + (size_t)(arid >> 1) * DDIM) : nullptr;
    int bk = tid >> 3, bn = tid & 7;             // B: k-row, 8-wide n chunk
    const __half* bgp = g_wg16 + ((size_t)e * DDIM + bk) * IDIM + n0 + bn*8;
    const __half* bup = g_wu16 + ((size_t)e * DDIM + bk) * IDIM + n0 + bn*8;

    int wm = wid & 1, wn = wid >> 1;             // warp tile 64m x 16n per matrix
    int g = lane >> 2, tig = lane & 3;
    int q = lane >> 3;
    int rA = (q & 1) * 8 + (lane & 7);
    int cA = (q >> 1) * 8;
    int rB = lane & 15;

    uint32_t as_s = sgen(&As[0][0]), bg_s = sgen(&Bg[0][0]), bu_s = sgen(&Bu[0][0]);
    const uint32_t ABUF = 128*A_ST2*2, BBUF = 32*B1_ST2*2;
    uint32_t abase = as_s + ((wm*64 + rA)*A_ST2 + cA)*2;
    uint32_t gbase = bg_s + (rB*B1_ST2 + wn*16)*2;
    uint32_t ubase = bu_s + (rB*B1_ST2 + wn*16)*2;

    float cg[4][2][4], cu[4][2][4];
#pragma unroll
    for (int a = 0; a < 4; a++)
#pragma unroll
        for (int b = 0; b < 2; b++)
#pragma unroll
            for (int c = 0; c < 4; c++) { cg[a][b][c] = 0.f; cu[a][b][c] = 0.f; }

    uint4 pa0, pa1, pgv, puv;

#define LOADR1(KT) do {                                                         \
    int kf_ = (KT) * 32;                                                        \
    if (aptr) {                                                                 \
        pa0 = *(const uint4*)(aptr + kf_ + ach);                                \
        pa1 = *(const uint4*)(aptr + kf_ + ach + 8);                            \
    } else { pa0 = make_uint4(0,0,0,0); pa1 = pa0; }                            \
    pgv = *(const uint4*)(bgp + (size_t)kf_ * IDIM);                            \
    puv = *(const uint4*)(bup + (size_t)kf_ * IDIM);                            \
} while (0)

#define STS1(B) do {                                                            \
    *(uint4*)&As[B][ar*A_ST2 + ach]     = pa0;                                  \
    *(uint4*)&As[B][ar*A_ST2 + ach + 8] = pa1;                                  \
    *(uint4*)&Bg[B][bk*B1_ST2 + bn*8]   = pgv;                                  \
    *(uint4*)&Bu[B][bk*B1_ST2 + bn*8]   = puv;                                  \
} while (0)

#define COMP1(B) do {                                                           \
    uint32_t ab_ = abase + (B)*ABUF;                                            \
    uint32_t gb_ = gbase + (B)*BBUF;                                            \
    uint32_t ub_ = ubase + (B)*BBUF;                                            \
    _Pragma("unroll")                                                           \
    for (int sp = 0; sp < 2; sp++) {                                            \
        uint32_t af[4][4], gf[2][2], uf[2][2];                                  \
        _Pragma("unroll")                                                       \
        for (int mi = 0; mi < 4; mi++)                                          \
            ldm4(af[mi], ab_ + (mi*16*A_ST2 + sp*16)*2);                        \
        _Pragma("unroll")                                                       \
        for (int p = 0; p < 2; p++) {                                           \
            ldm2t(gf[p], gb_ + (sp*16*B1_ST2 + p*8)*2);                         \
            ldm2t(uf[p], ub_ + (sp*16*B1_ST2 + p*8)*2);                         \
        }                                                                       \
        _Pragma("unroll")                                                       \
        for (int p = 0; p < 2; p++)                                             \
            _Pragma("unroll")                                                   \
            for (int mi = 0; mi < 4; mi++) {                                    \
                mmaf16(cg[mi][p], af[mi], gf[p]);                               \
                mmaf16(cu[mi][p], af[mi], uf[p]);                               \
            }                                                                   \
    }                                                                           \
} while (0)

    LOADR1(0);
    STS1(0);
    __syncthreads();
    for (int kt = 0; kt < NT1; kt++) {
        bool pf = (kt + 1 < NT1);
        if (pf) LOADR1(kt + 1);
        COMP1(kt & 1);
        if (pf) STS1((kt + 1) & 1);
        __syncthreads();
    }

    // epilogue: h = silu(gate)*up -> fp16
#pragma unroll
    for (int mi = 0; mi < 4; mi++) {
#pragma unroll
        for (int rh = 0; rh < 2; rh++) {
            int m = wm*64 + mi*16 + g + rh*8;
            int rid = rows_s[m];
            if (rid < 0) continue;
            __half2* hp = (__half2*)(g_h + (size_t)rid * IDIM + n0 + wn*16 + 2*tig);
#pragma unroll
            for (int p = 0; p < 2; p++) {
                float gv0 = cg[mi][p][rh*2+0], gv1 = cg[mi][p][rh*2+1];
                float uv0 = cu[mi][p][rh*2+0], uv1 = cu[mi][p][rh*2+1];
                float h0 = gv0 / (1.f + expf(-gv0)) * uv0;
                float h1 = gv1 / (1.f + expf(-gv1)) * uv1;
                hp[p*4] = __floats2half2_rn(h0, h1);
            }
        }
    }
}

// ---------------- GEMM2: 128 x 128 x 4096, 2 CTA/SM, direct atomic output ----------------
__global__ void __launch_bounds__(256, 2) gemm2_mma(float* __restrict__ out) {
    __shared__ __align__(16) __half As[2][128*A_ST2];
    __shared__ __align__(16) __half Bs[2][32*B2_ST2];
    __shared__ int rows_s[128];

    int e = blockIdx.z;
    int cnt = g_cnt[e];
    int m0 = blockIdx.x * 128;
    if (m0 >= cnt) return;
    int n0 = blockIdx.y * 128;

    int tid = threadIdx.x, wid = tid >> 5, lane = tid & 31;
    if (tid < 128) rows_s[tid] = (m0 + tid < cnt) ? g_list[e*NTOK + m0 + tid] : -1;
    __syncthreads();

    int ar = tid >> 1, ach = (tid & 1) * 16;
    int arid = rows_s[ar];
    const __half* aptr = (arid >= 0) ? (g_h + (size_t)arid * IDIM) : nullptr;
    int bk = tid >> 3, bn = tid & 7;             // 16-wide n chunk
    const __half* bp = g_wd16 + ((size_t)e * IDIM + bk) * DDIM + n0 + bn*16;

    int wm = wid & 1, wn = wid >> 1;             // warp tile 64m x 32n
    int g = lane >> 2, tig = lane & 3;
    int q = lane >> 3;
    int rA = (q & 1) * 8 + (lane & 7);
    int cA = (q >> 1) * 8;
    int rB = lane & 15;

    uint32_t as_s = sgen(&As[0][0]), bs_s = sgen(&Bs[0][0]);
    const uint32_t ABUF = 128*A_ST2*2, BBUF = 32*B2_ST2*2;
    uint32_t abase = as_s + ((wm*64 + rA)*A_ST2 + cA)*2;
    uint32_t bbase = bs_s + (rB*B2_ST2 + wn*32)*2;

    float cc[4][4][4];
#pragma unroll
    for (int a = 0; a < 4; a++)
#pragma unroll
        for (int b = 0; b < 4; b++)
#pragma unroll
            for (int c = 0; c < 4; c++) cc[a][b][c] = 0.f;

    uint4 pa0, pa1, pb0, pb1;

#define LOADR2(KT) do {                                                         \
    int kf_ = (KT) * 32;                                                        \
    if (aptr) {                                                                 \
        pa0 = *(const uint4*)(aptr + kf_ + ach);                                \
        pa1 = *(const uint4*)(aptr + kf_ + ach + 8);                            \
    } else { pa0 = make_uint4(0,0,0,0); pa1 = pa0; }                            \
    pb0 = *(const uint4*)(bp + (size_t)kf_ * DDIM);                             \
    pb1 = *(const uint4*)(bp + (size_t)kf_ * DDIM + 8);                         \
} while (0)

#define STS2(B) do {                                                            \
    *(uint4*)&As[B][ar*A_ST2 + ach]       = pa0;                                \
    *(uint4*)&As[B][ar*A_ST2 + ach + 8]   = pa1;                                \
    *(uint4*)&Bs[B][bk*B2_ST2 + bn*16]     = pb0;                               \
    *(uint4*)&Bs[B][bk*B2_ST2 + bn*16 + 8] = pb1;                               \
} while (0)

#define COMP2(B) do {                                                           \
    uint32_t ab_ = abase + (B)*ABUF;                                            \
    uint32_t bb_ = bbase + (B)*BBUF;                                            \
    _Pragma("unroll")                                                           \
    for (int sp = 0; sp < 2; sp++) {                                            \
        uint32_t af[4][4], bf[4][2];                                            \
        _Pragma("unroll")                                                       \
        for (int mi = 0; mi < 4; mi++)                                          \
            ldm4(af[mi], ab_ + (mi*16*A_ST2 + sp*16)*2);                        \
        _Pragma("unroll")                                                       \
        for (int p = 0; p < 4; p++)                                             \
            ldm2t(bf[p], bb_ + (sp*16*B2_ST2 + p*8)*2);                         \
        _Pragma("unroll")                                                       \
        for (int p = 0; p < 4; p++)                                             \
            _Pragma("unroll")                                                   \
            for (int mi = 0; mi < 4; mi++)                                      \
                mmaf16(cc[mi][p], af[mi], bf[p]);                               \
    }                                                                           \
} while (0)

    LOADR2(0);
    STS2(0);
    __syncthreads();
    for (int kt = 0; kt < NT2; kt++) {
        bool pf = (kt + 1 < NT2);
        if (pf) LOADR2(kt + 1);
        COMP2(kt & 1);
        if (pf) STS2((kt + 1) & 1);
        __syncthreads();
    }

    // epilogue: out[token] += w * v  (exactly 2 atomic adds per element; two-term
    // fp add is commutative -> deterministic)
#pragma unroll
    for (int mi = 0; mi < 4; mi++) {
#pragma unroll
        for (int rh = 0; rh < 2; rh++) {
            int m = wm*64 + mi*16 + g + rh*8;
            int rid = rows_s[m];
            if (rid < 0) continue;
            float w = g_rw[rid];
            float* yp = out + (size_t)(rid >> 1) * DDIM + n0 + wn*32 + 2*tig;
#pragma unroll
            for (int p = 0; p < 4; p++) {
                atomicAdd(yp + p*8,     cc[mi][p][rh*2+0] * w);
                atomicAdd(yp + p*8 + 1, cc[mi][p][rh*2+1] * w);
            }
        }
    }
}

// ---------------- aux ----------------
__global__ void finalize_kernel(float* __restrict__ out, int has_aux) {
    __shared__ float fp[NE];
    int t = threadIdx.x;
    if (t < NE) {
        float s = 0.f;
        for (int b = 0; b < 1024; b++) s += g_pp[b*NE + t];
        float pmean = s / (float)NTOK;
        float f = (float)g_cnt[t] / (float)NROWS;
        fp[t] = f * pmean;
    }
    __syncthreads();
    if (t == 0 && has_aux) {
        float a = 0.f;
        for (int e = 0; e < NE; e++) a += fp[e];
        out[OUT_ELEMS] = 0.02f * (float)NE * a;
    }
}

extern "C" void kernel_launch(void* const* d_in, const int* in_sizes, int n_in,
                              void* d_out, int out_size) {
    const float* x     = (const float*)d_in[0];
    const float* wgate = (const float*)d_in[1];
    const float* wg    = (const float*)d_in[2];
    const float* wu    = (const float*)d_in[3];
    const float* wd    = (const float*)d_in[4];
    float* out = (float*)d_out;

    zero_kernel<<<1, 32>>>();
    zero_out_kernel<<<OUT_ELEMS/1024, 256>>>(out);
    router_kernel<<<1024, 256>>>(x, wgate);
    conv_x<<<NTOK*DDIM/2048, 256>>>(x);
    conv_wg<<<NE*DDIM*IDIM/2048, 256>>>(wg);
    conv_wu<<<NE*DDIM*IDIM/2048, 256>>>(wu);
    conv_wd<<<NE*IDIM*DDIM/2048, 256>>>(wd);
    gemm1_mma<<<dim3(64, 64, 8), 256>>>();
    gemm2_mma<<<dim3(64, 8, 8), 256>>>(out);
    finalize_kernel<<<1, 32>>>(out, out_size > OUT_ELEMS ? 1 : 0);
}

// round 17
// speedup vs baseline: 1.4246x; 1.0093x over previous
#include <cuda_runtime.h>
#include <cuda_fp16.h>
#include <math.h>
#include <stdint.h>

#define NE 8
#define DDIM 1024
#define IDIM 4096
#define NTOK 8192
#define NROWS (NTOK*2)
#define OUT_ELEMS (NTOK*DDIM)

// ---------------- scratch (device globals; ONLY referenced from device code) ----------------
__device__ int   g_cnt[NE];
__device__ int   g_list[NE*NTOK];
__device__ float g_rw[NROWS];
__device__ float g_pp[1024*NE];
__device__ __half g_h[NROWS*IDIM];       // fp16 h (gemm2 A operand)
__device__ __half g_x16[NTOK*DDIM];      // fp16 x
__device__ __half g_wg16[NE*DDIM*IDIM];  // fp16 weights
__device__ __half g_wu16[NE*DDIM*IDIM];
__device__ __half g_wd16[NE*IDIM*DDIM];

// ---------------- helpers ----------------
__device__ __forceinline__ uint32_t ph2(float a, float b) {
    __half2 h = __floats2half2_rn(a, b);
    return *reinterpret_cast<uint32_t*>(&h);
}
__device__ __forceinline__ uint4 pk8(float4 a, float4 b) {
    return make_uint4(ph2(a.x,a.y), ph2(a.z,a.w), ph2(b.x,b.y), ph2(b.z,b.w));
}
__device__ __forceinline__ void ldm4(uint32_t* r, uint32_t a) {
    asm volatile("ldmatrix.sync.aligned.m8n8.x4.shared.b16 {%0,%1,%2,%3}, [%4];"
        : "=r"(r[0]), "=r"(r[1]), "=r"(r[2]), "=r"(r[3]) : "r"(a));
}
__device__ __forceinline__ void ldm4t(uint32_t* r, uint32_t a) {
    asm volatile("ldmatrix.sync.aligned.m8n8.x4.trans.shared.b16 {%0,%1,%2,%3}, [%4];"
        : "=r"(r[0]), "=r"(r[1]), "=r"(r[2]), "=r"(r[3]) : "r"(a));
}
__device__ __forceinline__ void mmaf16(float* c, const uint32_t* a, const uint32_t* b) {
    asm volatile(
        "mma.sync.aligned.m16n8k16.row.col.f32.f16.f16.f32 "
        "{%0,%1,%2,%3}, {%4,%5,%6,%7}, {%8,%9}, {%0,%1,%2,%3};"
        : "+f"(c[0]), "+f"(c[1]), "+f"(c[2]), "+f"(c[3])
        : "r"(a[0]), "r"(a[1]), "r"(a[2]), "r"(a[3]), "r"(b[0]), "r"(b[1]));
}
__device__ __forceinline__ uint32_t sgen(const void* p) {
    return (uint32_t)__cvta_generic_to_shared(p);
}

// ---------------- small kernels ----------------
__global__ void zero_kernel() { if (threadIdx.x < NE) g_cnt[threadIdx.x] = 0; }

__global__ void __launch_bounds__(256) zero_out_kernel(float* __restrict__ out) {
    size_t i = (size_t)blockIdx.x * 256 + threadIdx.x;
    ((float4*)out)[i] = make_float4(0.f, 0.f, 0.f, 0.f);
}

// merged fp32->fp16 prepass for wg, wu, wd, x (block ranges select tensor)
#define WBLK (NE*DDIM*IDIM/2048)     // 16384 blocks per weight tensor
#define XBLK (NTOK*DDIM/2048)        // 4096 blocks for x
__global__ void __launch_bounds__(256) conv_all(const float* __restrict__ x,
                                                const float* __restrict__ wg,
                                                const float* __restrict__ wu,
                                                const float* __restrict__ wd) {
    size_t bid = blockIdx.x;
    const float* src; __half* dst; size_t off;
    if (bid < WBLK)            { src = wg; dst = g_wg16; off = bid; }
    else if (bid < 2*WBLK)     { src = wu; dst = g_wu16; off = bid - WBLK; }
    else if (bid < 3*WBLK)     { src = wd; dst = g_wd16; off = bid - 2*WBLK; }
    else                       { src = x;  dst = g_x16;  off = bid - 3*WBLK; }
    size_t i = (off * 256 + threadIdx.x) * 8;
    float4 a = *(const float4*)(src + i);
    float4 b = *(const float4*)(src + i + 4);
    *(uint4*)(dst + i) = pk8(a, b);
}

__global__ void __launch_bounds__(256) router_kernel(const float* __restrict__ x,
                                                     const float* __restrict__ wgate) {
    __shared__ float sw[NE*DDIM];
    __shared__ float sprob[8][NE];
    int tid = threadIdx.x;
    for (int i = tid; i < NE*DDIM; i += 256) sw[i] = wgate[i];
    __syncthreads();
    int warp = tid >> 5, lane = tid & 31;
    int n = blockIdx.x * 8 + warp;
    const float* xr = x + (size_t)n * DDIM;
    float xv[32];
#pragma unroll
    for (int i = 0; i < 32; i++) xv[i] = xr[i*32 + lane];
    float p[NE]; float mx = -1e30f;
#pragma unroll
    for (int e = 0; e < NE; e++) {
        float acc = 0.f;
        const float* swe = sw + e*DDIM;
#pragma unroll
        for (int i = 0; i < 32; i++) acc += xv[i] * swe[i*32 + lane];
#pragma unroll
        for (int o = 16; o > 0; o >>= 1) acc += __shfl_xor_sync(0xffffffffu, acc, o);
        p[e] = acc; mx = fmaxf(mx, acc);
    }
    float se = 0.f;
#pragma unroll
    for (int e = 0; e < NE; e++) { p[e] = expf(p[e] - mx); se += p[e]; }
    float inv = 1.f / se;
#pragma unroll
    for (int e = 0; e < NE; e++) p[e] *= inv;
    int e0 = 0;
#pragma unroll
    for (int e = 1; e < NE; e++) if (p[e] > p[e0]) e0 = e;
    int e1 = (e0 == 0) ? 1 : 0;
#pragma unroll
    for (int e = 0; e < NE; e++) if (e != e0 && e != e1 && p[e] > p[e1]) e1 = e;
    if (lane == 0) {
        float w0 = p[e0], w1 = p[e1], s = w0 + w1;
        g_rw[n*2] = w0 / s; g_rw[n*2+1] = w1 / s;
        int p0 = atomicAdd(&g_cnt[e0], 1); g_list[e0*NTOK + p0] = n*2;
        int p1 = atomicAdd(&g_cnt[e1], 1); g_list[e1*NTOK + p1] = n*2 + 1;
#pragma unroll
        for (int e = 0; e < NE; e++) sprob[warp][e] = p[e];
    }
    __syncthreads();
    if (tid == 0) {
#pragma unroll
        for (int e = 0; e < NE; e++) {
            float s = 0.f;
            for (int w = 0; w < 8; w++) s += sprob[w][e];
            g_pp[blockIdx.x*NE + e] = s;
        }
    }
}

// ---------------- GEMM geometry (fp16 smem, static) ----------------
#define A_ST2  40            // 128x32 fp16, 80B rows
#define B1_ST2 72            // 32x64 fp16, 144B rows
#define B2_ST2 136           // 32x128 fp16, 272B rows
#define NT1 32
#define NT2 128

// ---------------- GEMM1: 128 x (64g + 64u) x 1024, 2 CTA/SM ----------------
__global__ void __launch_bounds__(256, 2) gemm1_mma() {
    __shared__ __align__(16) __half As[2][128*A_ST2];
    __shared__ __align__(16) __half Bg[2][32*B1_ST2];
    __shared__ __align__(16) __half Bu[2][32*B1_ST2];
    __shared__ int rows_s[128];

    int e = blockIdx.z;
    int cnt = g_cnt[e];
    int m0 = blockIdx.x * 128;
    if (m0 >= cnt) return;
    int n0 = blockIdx.y * 64;

    int tid = threadIdx.x, wid = tid >> 5, lane = tid & 31;
    if (tid < 128) rows_s[tid] = (m0 + tid < cnt) ? g_list[e*NTOK + m0 + tid] : -1;
    __syncthreads();

    int ar = tid >> 1, ach = (tid & 1) * 16;
    int arid = rows_s[ar];
    const __half* aptr = (arid >= 0) ? (g_x16 + (size_t)(arid >> 1) * DDIM) : nullptr;
    int bk = tid >> 3, bn = tid & 7;
    const __half* bgp = g_wg16 + ((size_t)e * DDIM + bk) * IDIM + n0 + bn*8;
    const __half* bup = g_wu16 + ((size_t)e * DDIM + bk) * IDIM + n0 + bn*8;

    int wm = wid & 1, wn = wid >> 1;             // warp tile 64m x 16n per matrix
    int g = lane >> 2, tig = lane & 3;
    int q = lane >> 3;
    int rA = (q & 1) * 8 + (lane & 7);
    int cA = (q >> 1) * 8;
    // ldm4t lane mapping for B: groups of 8 lanes -> tiles (p0,klo),(p0,khi),(p1,klo),(p1,khi)
    int rB4 = (lane & 7) + ((lane >> 3) & 1) * 8;
    int cB4 = ((lane >> 4) & 1) * 8;

    uint32_t as_s = sgen(&As[0][0]), bg_s = sgen(&Bg[0][0]), bu_s = sgen(&Bu[0][0]);
    const uint32_t ABUF = 128*A_ST2*2, BBUF = 32*B1_ST2*2;
    uint32_t abase = as_s + ((wm*64 + rA)*A_ST2 + cA)*2;
    uint32_t gbase = bg_s + (rB4*B1_ST2 + wn*16 + cB4)*2;
    uint32_t ubase = bu_s + (rB4*B1_ST2 + wn*16 + cB4)*2;

    float cg[4][2][4], cu[4][2][4];
#pragma unroll
    for (int a = 0; a < 4; a++)
#pragma unroll
        for (int b = 0; b < 2; b++)
#pragma unroll
            for (int c = 0; c < 4; c++) { cg[a][b][c] = 0.f; cu[a][b][c] = 0.f; }

    uint4 pa0, pa1, pgv, puv;

#define LOADR1(KT) do {                                                         \
    int kf_ = (KT) * 32;                                                        \
    if (aptr) {                                                                 \
        pa0 = *(const uint4*)(aptr + kf_ + ach);                                \
        pa1 = *(const uint4*)(aptr + kf_ + ach + 8);                            \
    } else { pa0 = make_uint4(0,0,0,0); pa1 = pa0; }                            \
    pgv = *(const uint4*)(bgp + (size_t)kf_ * IDIM);                            \
    puv = *(const uint4*)(bup + (size_t)kf_ * IDIM);                            \
} while (0)

#define STS1(B) do {                                                            \
    *(uint4*)&As[B][ar*A_ST2 + ach]     = pa0;                                  \
    *(uint4*)&As[B][ar*A_ST2 + ach + 8] = pa1;                                  \
    *(uint4*)&Bg[B][bk*B1_ST2 + bn*8]   = pgv;                                  \
    *(uint4*)&Bu[B][bk*B1_ST2 + bn*8]   = puv;                                  \
} while (0)

#define COMP1(B) do {                                                           \
    uint32_t ab_ = abase + (B)*ABUF;                                            \
    uint32_t gb_ = gbase + (B)*BBUF;                                            \
    uint32_t ub_ = ubase + (B)*BBUF;                                            \
    _Pragma("unroll")                                                           \
    for (int sp = 0; sp < 2; sp++) {                                            \
        uint32_t af[4][4], gf[4], uf[4];                                        \
        _Pragma("unroll")                                                       \
        for (int mi = 0; mi < 4; mi++)                                          \
            ldm4(af[mi], ab_ + (mi*16*A_ST2 + sp*16)*2);                        \
        ldm4t(gf, gb_ + (sp*16*B1_ST2)*2);                                      \
        ldm4t(uf, ub_ + (sp*16*B1_ST2)*2);                                      \
        _Pragma("unroll")                                                       \
        for (int p = 0; p < 2; p++)                                             \
            _Pragma("unroll")                                                   \
            for (int mi = 0; mi < 4; mi++) {                                    \
                mmaf16(cg[mi][p], af[mi], gf + p*2);                            \
                mmaf16(cu[mi][p], af[mi], uf + p*2);                            \
            }                                                                   \
    }                                                                           \
} while (0)

    LOADR1(0);
    STS1(0);
    __syncthreads();
    for (int kt = 0; kt < NT1; kt++) {
        bool pf = (kt + 1 < NT1);
        if (pf) LOADR1(kt + 1);
        COMP1(kt & 1);
        if (pf) STS1((kt + 1) & 1);
        __syncthreads();
    }

    // epilogue: h = silu(gate)*up -> fp16
#pragma unroll
    for (int mi = 0; mi < 4; mi++) {
#pragma unroll
        for (int rh = 0; rh < 2; rh++) {
            int m = wm*64 + mi*16 + g + rh*8;
            int rid = rows_s[m];
            if (rid < 0) continue;
            __half2* hp = (__half2*)(g_h + (size_t)rid * IDIM + n0 + wn*16 + 2*tig);
#pragma unroll
            for (int p = 0; p < 2; p++) {
                float gv0 = cg[mi][p][rh*2+0], gv1 = cg[mi][p][rh*2+1];
                float uv0 = cu[mi][p][rh*2+0], uv1 = cu[mi][p][rh*2+1];
                float h0 = gv0 / (1.f + expf(-gv0)) * uv0;
                float h1 = gv1 / (1.f + expf(-gv1)) * uv1;
                hp[p*4] = __floats2half2_rn(h0, h1);
            }
        }
    }
}

// ---------------- GEMM2: 128 x 128 x 4096, 2 CTA/SM, direct atomic output ----------------
__global__ void __launch_bounds__(256, 2) gemm2_mma(float* __restrict__ out) {
    __shared__ __align__(16) __half As[2][128*A_ST2];
    __shared__ __align__(16) __half Bs[2][32*B2_ST2];
    __shared__ int rows_s[128];

    int e = blockIdx.z;
    int cnt = g_cnt[e];
    int m0 = blockIdx.x * 128;
    if (m0 >= cnt) return;
    int n0 = blockIdx.y * 128;

    int tid = threadIdx.x, wid = tid >> 5, lane = tid & 31;
    if (tid < 128) rows_s[tid] = (m0 + tid < cnt) ? g_list[e*NTOK + m0 + tid] : -1;
    __syncthreads();

    int ar = tid >> 1, ach = (tid & 1) * 16;
    int arid = rows_s[ar];
    const __half* aptr = (arid >= 0) ? (g_h + (size_t)arid * IDIM) : nullptr;
    int bk = tid >> 3, bn = tid & 7;
    const __half* bp = g_wd16 + ((size_t)e * IDIM + bk) * DDIM + n0 + bn*16;

    int wm = wid & 1, wn = wid >> 1;             // warp tile 64m x 32n
    int g = lane >> 2, tig = lane & 3;
    int q = lane >> 3;
    int rA = (q & 1) * 8 + (lane & 7);
    int cA = (q >> 1) * 8;
    int rB4 = (lane & 7) + ((lane >> 3) & 1) * 8;
    int cB4 = ((lane >> 4) & 1) * 8;

    uint32_t as_s = sgen(&As[0][0]), bs_s = sgen(&Bs[0][0]);
    const uint32_t ABUF = 128*A_ST2*2, BBUF = 32*B2_ST2*2;
    uint32_t abase = as_s + ((wm*64 + rA)*A_ST2 + cA)*2;
    uint32_t bbase = bs_s + (rB4*B2_ST2 + wn*32 + cB4)*2;

    float cc[4][4][4];
#pragma unroll
    for (int a = 0; a < 4; a++)
#pragma unroll
        for (int b = 0; b < 4; b++)
#pragma unroll
            for (int c = 0; c < 4; c++) cc[a][b][c] = 0.f;

    uint4 pa0, pa1, pb0, pb1;

#define LOADR2(KT) do {                                                         \
    int kf_ = (KT) * 32;                                                        \
    if (aptr) {                                                                 \
        pa0 = *(const uint4*)(aptr + kf_ + ach);                                \
        pa1 = *(const uint4*)(aptr + kf_ + ach + 8);                            \
    } else { pa0 = make_uint4(0,0,0,0); pa1 = pa0; }                            \
    pb0 = *(const uint4*)(bp + (size_t)kf_ * DDIM);                             \
    pb1 = *(const uint4*)(bp + (size_t)kf_ * DDIM + 8);                         \
} while (0)

#define STS2(B) do {                                                            \
    *(uint4*)&As[B][ar*A_ST2 + ach]       = pa0;                                \
    *(uint4*)&As[B][ar*A_ST2 + ach + 8]   = pa1;                                \
    *(uint4*)&Bs[B][bk*B2_ST2 + bn*16]     = pb0;                               \
    *(uint4*)&Bs[B][bk*B2_ST2 + bn*16 + 8] = pb1;                               \
} while (0)

#define COMP2(B) do {                                                           \
    uint32_t ab_ = abase + (B)*ABUF;                                            \
    uint32_t bb_ = bbase + (B)*BBUF;                                            \
    _Pragma("unroll")                                                           \
    for (int sp = 0; sp < 2; sp++) {                                            \
        uint32_t af[4][4], bf[8];                                               \
        _Pragma("unroll")                                                       \
        for (int mi = 0; mi < 4; mi++)                                          \
            ldm4(af[mi], ab_ + (mi*16*A_ST2 + sp*16)*2);                        \
        ldm4t(bf,     bb_ + (sp*16*B2_ST2)*2);                                  \
        ldm4t(bf + 4, bb_ + (sp*16*B2_ST2 + 16)*2);                             \
        _Pragma("unroll")                                                       \
        for (int p = 0; p < 4; p++)                                             \
            _Pragma("unroll")                                                   \
            for (int mi = 0; mi < 4; mi++)                                      \
                mmaf16(cc[mi][p], af[mi], bf + p*2);                            \
    }                                                                           \
} while (0)

    LOADR2(0);
    STS2(0);
    __syncthreads();
    for (int kt = 0; kt < NT2; kt++) {
        bool pf = (kt + 1 < NT2);
        if (pf) LOADR2(kt + 1);
        COMP2(kt & 1);
        if (pf) STS2((kt + 1) & 1);
        __syncthreads();
    }

    // epilogue: out[token] += w * v  (exactly 2 atomic adds per element -> deterministic)
#pragma unroll
    for (int mi = 0; mi < 4; mi++) {
#pragma unroll
        for (int rh = 0; rh < 2; rh++) {
            int m = wm*64 + mi*16 + g + rh*8;
            int rid = rows_s[m];
            if (rid < 0) continue;
            float w = g_rw[rid];
            float* yp = out + (size_t)(rid >> 1) * DDIM + n0 + wn*32 + 2*tig;
#pragma unroll
            for (int p = 0; p < 4; p++) {
                atomicAdd(yp + p*8,     cc[mi][p][rh*2+0] * w);
                atomicAdd(yp + p*8 + 1, cc[mi][p][rh*2+1] * w);
            }
        }
    }
}

// ---------------- aux ----------------
__global__ void finalize_kernel(float* __restrict__ out, int has_aux) {
    __shared__ float fp[NE];
    int t = threadIdx.x;
    if (t < NE) {
        float s = 0.f;
        for (int b = 0; b < 1024; b++) s += g_pp[b*NE + t];
        float pmean = s / (float)NTOK;
        float f = (float)g_cnt[t] / (float)NROWS;
        fp[t] = f * pmean;
    }
    __syncthreads();
    if (t == 0 && has_aux) {
        float a = 0.f;
        for (int e = 0; e < NE; e++) a += fp[e];
        out[OUT_ELEMS] = 0.02f * (float)NE * a;
    }
}

extern "C" void kernel_launch(void* const* d_in, const int* in_sizes, int n_in,
                              void* d_out, int out_size) {
    const float* x     = (const float*)d_in[0];
    const float* wgate = (const float*)d_in[1];
    const float* wg    = (const float*)d_in[2];
    const float* wu    = (const float*)d_in[3];
    const float* wd    = (const float*)d_in[4];
    float* out = (float*)d_out;

    zero_kernel<<<1, 32>>>();
    zero_out_kernel<<<OUT_ELEMS/1024, 256>>>(out);
    router_kernel<<<1024, 256>>>(x, wgate);
    conv_all<<<3*WBLK + XBLK, 256>>>(x, wg, wu, wd);
    gemm1_mma<<<dim3(64, 64, 8), 256>>>();
    gemm2_mma<<<dim3(64, 8, 8), 256>>>(out);
    finalize_kernel<<<1, 32>>>(out, out_size > OUT_ELEMS ? 1 : 0);
}